// round 10
// baseline (speedup 1.0000x reference)
#include <cuda_runtime.h>
#include <cuda_bf16.h>

// Two-launch top-10% mask (R7 structure + fine-grained sampled band).
// K1 (mega): blocks 0-127 sample 1/16 -> 65536-bin GLOBAL fine histogram
//            (2^14-key bins); last-done block per matrix computes band
//            [Tlo,Thi) via chunk-sum hierarchy (+-2500-sample margins, 8
//            sigma); other blocks spin; then ALL blocks run the fused pass:
//            provisional mask (k>=Tlo -> 1), count k>=Thi, compact band
//            elements (~110K/matrix).
// K2 (refine): 32 blocks/matrix with device grid-barriers: two narrowing
//            stages over candidates -> exact threshold key T + residual z;
//            final pass zeroes k<T, collects k==T; block 0 does the stable
//            argsort tie fixup; guarded single-block rescue on any bound
//            failure (correctness unconditional).
// State self-cleans across graph replays (K2 resets K1 state; K1 resets
// K2's barrier counters - ordering via launch boundary).

#define SHIFTF   14
#define NBF2     (1u << 16)
#define NCHK     128
#define CHKSZ    512
#define NST      2048
#define CAND_CAP (1u << 19)
#define BLK_CAP  1024
#define EQ_CAP   4096

__device__ unsigned g_shist[2][NBF2];
__device__ unsigned g_ch[2][2][NST];
__device__ unsigned g_Tlo[2], g_Thi[2];
__device__ unsigned g_sdone[2];
__device__ unsigned g_ready[2];
__device__ unsigned g_cand_idx[2][CAND_CAP];
__device__ unsigned g_cand_key[2][CAND_CAP];
__device__ unsigned g_cand_cnt[2];
__device__ unsigned g_hiCnt[2];
__device__ unsigned g_fail[2];
__device__ unsigned g_bar[2][8];
__device__ unsigned g_eq[2][EQ_CAP];
__device__ unsigned g_eq_cnt[2];

__device__ __forceinline__ unsigned abskey(float v) {
    return __float_as_uint(v) & 0x7FFFFFFFu;
}

// 512-thread inclusive scan of sh[0..511].
__device__ __forceinline__ void scan512(unsigned* sh) {
    const int t = threadIdx.x;
    for (int off = 1; off < 512; off <<= 1) {
        unsigned x = (t >= off) ? sh[t - off] : 0u;
        __syncthreads();
        sh[t] += x;
        __syncthreads();
    }
}

// Find fine bin containing ascending sample rank (Stot - C). Requires
// sc[0..127] = inclusive-scanned chunk sums. Whole 512-thread block.
__device__ unsigned fine_cut(int m, const unsigned* sc, unsigned C, unsigned* sh) {
    __shared__ unsigned f_chunk, f_rank, f_bin;
    const int t = threadIdx.x;
    if (t == 0) { f_chunk = 0; f_rank = 0; f_bin = 0; }
    __syncthreads();
    unsigned S = sc[NCHK - 1];
    unsigned r = (S >= C) ? (S - C) : 0u;
    if (t < NCHK) {
        unsigned incl = sc[t];
        unsigned excl = t ? sc[t - 1] : 0u;
        if (excl <= r && r < incl) { f_chunk = (unsigned)t; f_rank = r - excl; }
    }
    __syncthreads();
    unsigned ch = f_chunk, rr = f_rank;
    unsigned b = g_shist[m][ch * CHKSZ + t];
    __syncthreads();
    sh[t] = b;
    __syncthreads();
    scan512(sh);
    {
        unsigned run = sh[t] - b;
        if (run <= rr && rr < run + b) f_bin = ch * CHKSZ + (unsigned)t;
    }
    __syncthreads();
    unsigned out = f_bin;
    __syncthreads();
    return out;
}

__global__ void __launch_bounds__(512)
mega_kernel(const float4* __restrict__ A, const float4* __restrict__ B,
            float4* __restrict__ out, int n4, int chunk,
            unsigned C_lo, unsigned C_hi) {
    __shared__ unsigned sh[512];
    __shared__ unsigned sc[NCHK];
    __shared__ unsigned s_idx[BLK_CAP];
    __shared__ unsigned s_key[BLK_CAP];
    __shared__ unsigned s_cnt, s_base, s_hi, s_flag;
    const int m = blockIdx.x & 1;
    const int t = threadIdx.x;

    // Reset K2's barrier counters for the NEXT refine launch.
    if (blockIdx.x == 0 && t < 16) ((unsigned*)g_bar)[t] = 0;

    // ---- sample phase (blocks 0..127; 64 per matrix) ----
    if (blockIdx.x < 128) {
        const float4* __restrict__ in = m ? B : A;
        int sbl = blockIdx.x >> 1;               // 0..63
        int beg = sbl * chunk, end = beg + chunk;
        for (int i = beg + t; i < end; i += 512) {
            float4 v = in[i];
            atomicAdd(&g_shist[m][abskey(v.x) >> SHIFTF], 1u);
            atomicAdd(&g_shist[m][abskey(v.y) >> SHIFTF], 1u);
            atomicAdd(&g_shist[m][abskey(v.z) >> SHIFTF], 1u);
            atomicAdd(&g_shist[m][abskey(v.w) >> SHIFTF], 1u);
        }
        __threadfence();
        __syncthreads();
        if (t == 0) s_flag = (atomicAdd(&g_sdone[m], 1u) == 63u) ? 1u : 0u;
        __syncthreads();
        if (s_flag) {
            __threadfence();
            // chunk sums: warp w handles chunks w, w+16, ... (coalesced)
            const int w = t >> 5, lane = t & 31;
            for (int c = w; c < NCHK; c += 16) {
                unsigned v = 0;
                #pragma unroll
                for (int k = 0; k < CHKSZ / 32; k++)
                    v += g_shist[m][c * CHKSZ + lane + k * 32];
                for (int off = 16; off > 0; off >>= 1)
                    v += __shfl_down_sync(0xFFFFFFFFu, v, off);
                if (lane == 0) sc[c] = v;
            }
            __syncthreads();
            // inclusive scan of sc[0..127] (threads 0..127)
            for (int off = 1; off < NCHK; off <<= 1) {
                unsigned x = (t < NCHK && t >= off) ? sc[t - off] : 0u;
                __syncthreads();
                if (t < NCHK) sc[t] += x;
                __syncthreads();
            }
            unsigned binA = fine_cut(m, sc, C_hi, sh);
            unsigned binB = fine_cut(m, sc, C_lo, sh);
            if (t == 0) {
                g_Tlo[m] = binA << SHIFTF;
                g_Thi[m] = (binB >= NBF2 - 1) ? 0xFFFFFFFFu
                                              : ((binB + 1u) << SHIFTF);
                __threadfence();
                atomicExch(&g_ready[m], 1u);
            }
        }
    }

    // ---- wait for band ----
    if (t == 0) {
        while (*(volatile unsigned*)&g_ready[m] == 0u) __nanosleep(128);
        s_cnt = 0; s_hi = 0;
    }
    __syncthreads();
    __threadfence();
    const unsigned Tlo = *(volatile unsigned*)&g_Tlo[m];
    const unsigned Thi = *(volatile unsigned*)&g_Thi[m];

    // ---- fused pass: mask write + hi count + band compaction ----
    const float4* __restrict__ in = m ? B : A;
    float4* __restrict__ dst = out + (size_t)m * (size_t)n4;
    unsigned hi = 0;
    const int stride = (gridDim.x >> 1) * blockDim.x;
    int i0 = (blockIdx.x >> 1) * blockDim.x + t;
    for (int i = i0; i < n4; i += 2 * stride) {
        int i2 = i + stride;
        float4 v0 = in[i];
        float4 v1 = (i2 < n4) ? in[i2] : make_float4(0.f, 0.f, 0.f, 0.f);
        float4 r0, r1;
        unsigned b0 = ((unsigned)i) << 2;
        unsigned b1 = ((unsigned)i2) << 2;
        unsigned k;

        k = abskey(v0.x); r0.x = (k >= Tlo) ? 1.0f : 0.0f; hi += (k >= Thi);
        if (k >= Tlo && k < Thi) { unsigned p = atomicAdd(&s_cnt, 1u); if (p < BLK_CAP) { s_idx[p] = b0;     s_key[p] = k; } }
        k = abskey(v0.y); r0.y = (k >= Tlo) ? 1.0f : 0.0f; hi += (k >= Thi);
        if (k >= Tlo && k < Thi) { unsigned p = atomicAdd(&s_cnt, 1u); if (p < BLK_CAP) { s_idx[p] = b0 + 1; s_key[p] = k; } }
        k = abskey(v0.z); r0.z = (k >= Tlo) ? 1.0f : 0.0f; hi += (k >= Thi);
        if (k >= Tlo && k < Thi) { unsigned p = atomicAdd(&s_cnt, 1u); if (p < BLK_CAP) { s_idx[p] = b0 + 2; s_key[p] = k; } }
        k = abskey(v0.w); r0.w = (k >= Tlo) ? 1.0f : 0.0f; hi += (k >= Thi);
        if (k >= Tlo && k < Thi) { unsigned p = atomicAdd(&s_cnt, 1u); if (p < BLK_CAP) { s_idx[p] = b0 + 3; s_key[p] = k; } }
        dst[i] = r0;

        if (i2 < n4) {
            k = abskey(v1.x); r1.x = (k >= Tlo) ? 1.0f : 0.0f; hi += (k >= Thi);
            if (k >= Tlo && k < Thi) { unsigned p = atomicAdd(&s_cnt, 1u); if (p < BLK_CAP) { s_idx[p] = b1;     s_key[p] = k; } }
            k = abskey(v1.y); r1.y = (k >= Tlo) ? 1.0f : 0.0f; hi += (k >= Thi);
            if (k >= Tlo && k < Thi) { unsigned p = atomicAdd(&s_cnt, 1u); if (p < BLK_CAP) { s_idx[p] = b1 + 1; s_key[p] = k; } }
            k = abskey(v1.z); r1.z = (k >= Tlo) ? 1.0f : 0.0f; hi += (k >= Thi);
            if (k >= Tlo && k < Thi) { unsigned p = atomicAdd(&s_cnt, 1u); if (p < BLK_CAP) { s_idx[p] = b1 + 2; s_key[p] = k; } }
            k = abskey(v1.w); r1.w = (k >= Tlo) ? 1.0f : 0.0f; hi += (k >= Thi);
            if (k >= Tlo && k < Thi) { unsigned p = atomicAdd(&s_cnt, 1u); if (p < BLK_CAP) { s_idx[p] = b1 + 3; s_key[p] = k; } }
            dst[i2] = r1;
        }
    }
    for (int off = 16; off > 0; off >>= 1) hi += __shfl_down_sync(0xFFFFFFFFu, hi, off);
    if ((t & 31) == 0 && hi) atomicAdd(&s_hi, hi);
    __syncthreads();
    if (t == 0) {
        if (s_hi) atomicAdd(&g_hiCnt[m], s_hi);
        unsigned c = s_cnt;
        if (c > BLK_CAP) { atomicExch(&g_fail[m], 1u); c = BLK_CAP; }
        s_cnt = c;
        s_base = atomicAdd(&g_cand_cnt[m], c);
    }
    __syncthreads();
    unsigned c = s_cnt, bpos = s_base;
    for (unsigned p = t; p < c; p += blockDim.x) {
        unsigned gp = bpos + p;
        if (gp < CAND_CAP) { g_cand_idx[m][gp] = s_idx[p]; g_cand_key[m][gp] = s_key[p]; }
    }
}

// Grid barrier over the nb blocks of matrix m (all co-resident: grid = 64).
__device__ __forceinline__ void gbar(int m, int ph, unsigned nb) {
    __syncthreads();
    if (threadIdx.x == 0) {
        __threadfence();
        atomicAdd(&g_bar[m][ph], 1u);
        while (*(volatile unsigned*)&g_bar[m][ph] < nb) __nanosleep(64);
        __threadfence();
    }
    __syncthreads();
}

// Single-block, slow, unconditionally-correct rescue (only on bound failure).
__device__ void rescue_block(const float* __restrict__ in, float* __restrict__ dst,
                             int n, unsigned target_top, unsigned* sh) {
    __shared__ unsigned r_lo, r_span, r_rank;
    const int t = threadIdx.x;
    if (t == 0) { r_lo = 0; r_span = 1u << 30; r_rank = (unsigned)n - target_top; }
    __syncthreads();
    while (r_span > 1) {
        unsigned lo = r_lo, span = r_span;
        unsigned s = (span > (unsigned)NST) ? (unsigned)(32 - __clz(span - 1) - 11) : 0u;
        for (int i = t; i < NST; i += 1024) sh[i] = 0;
        __syncthreads();
        for (int i = t; i < n; i += 1024) {
            unsigned d = abskey(in[i]) - lo;
            if (d < span) atomicAdd(&sh[d >> s], 1u);
        }
        __syncthreads();
        if (t == 0) {
            unsigned rank = r_rank, run = 0;
            for (int i = 0; i < NST; i++) {
                unsigned cc = sh[i];
                if (rank < run + cc) { r_lo = lo + ((unsigned)i << s); r_span = 1u << s; r_rank = rank - run; break; }
                run += cc;
            }
        }
        __syncthreads();
    }
    unsigned T = r_lo, z = r_rank;
    for (int i = t; i < n; i += 1024) {
        unsigned k = abskey(in[i]);
        if (k != T) dst[i] = (k > T) ? 1.0f : 0.0f;
    }
    __syncthreads();
    if (t == 0) {
        unsigned seen = 0;
        for (int i = 0; i < n; i++)
            if (abskey(in[i]) == T) { dst[i] = (seen < z) ? 0.0f : 1.0f; seen++; }
    }
    __syncthreads();
}

__global__ void __launch_bounds__(1024)
refine_kernel(const float* __restrict__ A, const float* __restrict__ B,
              float* __restrict__ out, int n, unsigned target_top) {
    __shared__ unsigned sh[NST];
    __shared__ unsigned s_sel, s_res;
    const int m = blockIdx.x & 1;
    const unsigned nb = gridDim.x >> 1;   // 32
    const unsigned bl = blockIdx.x >> 1;
    const int t = threadIdx.x;

    unsigned cnt_real = g_cand_cnt[m];
    unsigned cnt = min(cnt_real, CAND_CAP);
    unsigned hic = g_hiCnt[m];
    bool bad = (g_fail[m] != 0) || (cnt_real > CAND_CAP) ||
               (hic >= target_top) || (target_top - hic > cnt);
    unsigned rank = 0, lo = 0, span = 1;
    if (!bad) {
        unsigned keep = target_top - hic;
        rank = cnt - keep;
        lo = g_Tlo[m];
        span = g_Thi[m] - lo;
    }
    if (!bad && span > (1u << 22)) bad = true;
    const unsigned* __restrict__ keys = g_cand_key[m];
    const unsigned* __restrict__ idxs = g_cand_idx[m];
    float* __restrict__ dst = out + (size_t)m * (size_t)n;

    // two narrowing stages (2048 bins each; 2048^2 = 4M covers any sane band)
    for (int st = 0; st < 2; st++) {
        bool active = (!bad) && (span > 1);
        unsigned s = 0;
        if (active) {
            s = (span > (unsigned)NST) ? (unsigned)(32 - __clz(span - 1) - 11) : 0u;
            for (int i = t; i < NST; i += 1024) sh[i] = 0;
            __syncthreads();
            unsigned stride = nb * 1024u;
            for (unsigned c = bl * 1024u + t; c < cnt; c += stride) {
                unsigned d = keys[c] - lo;
                if (d < span) atomicAdd(&sh[d >> s], 1u);
            }
            __syncthreads();
            for (int i = t; i < NST; i += 1024) {
                unsigned v = sh[i];
                if (v) atomicAdd(&g_ch[m][st][i], v);
            }
        }
        gbar(m, st, nb);
        if (active) {
            unsigned l0 = g_ch[m][st][2 * t], l1 = g_ch[m][st][2 * t + 1];
            unsigned sum = l0 + l1;
            if (t == 0) { s_sel = 0; s_res = 0; }
            __syncthreads();
            sh[t] = sum;
            __syncthreads();
            for (int off = 1; off < 1024; off <<= 1) {
                unsigned x = (t >= off) ? sh[t - off] : 0u;
                __syncthreads();
                sh[t] += x;
                __syncthreads();
            }
            unsigned incl = sh[t], run = incl - sum;
            if (run <= rank && rank < run + l0)           { s_sel = 2 * t;     s_res = rank - run; }
            else if (run + l0 <= rank && rank < incl)     { s_sel = 2 * t + 1; s_res = rank - run - l0; }
            __syncthreads();
            lo += s_sel << s;
            span = 1u << s;
            rank = s_res;
            __syncthreads();
        }
    }
    if (!bad && span != 1) bad = true;

    // final candidate pass
    if (!bad) {
        const unsigned T = lo;
        unsigned stride = nb * 1024u;
        for (unsigned c = bl * 1024u + t; c < cnt; c += stride) {
            unsigned k = keys[c];
            if (k < T) {
                dst[idxs[c]] = 0.0f;
            } else if (k == T) {
                unsigned p = atomicAdd(&g_eq_cnt[m], 1u);
                if (p < EQ_CAP) g_eq[m][p] = idxs[c];
            }
        }
    }
    gbar(m, 2, nb);
    unsigned eq = g_eq_cnt[m];
    if (!bad && eq > EQ_CAP) bad = true;
    if (bl == 0) {
        if (!bad) {
            unsigned z = rank;
            for (unsigned e = t; e < eq; e += 1024) {
                unsigned idx = g_eq[m][e];
                unsigned c2 = 0;
                for (unsigned q = 0; q < eq; q++) c2 += (g_eq[m][q] < idx) ? 1u : 0u;
                if (c2 < z) dst[idx] = 0.0f;
            }
        } else {
            rescue_block(m ? B : A, dst, n, target_top, sh);
        }
    }
    gbar(m, 3, nb);

    // self-clean for next replay's mega_kernel (g_bar reset there instead)
    for (unsigned i = bl * 1024u + t; i < NBF2; i += nb * 1024u) g_shist[m][i] = 0;
    for (unsigned i = bl * 1024u + t; i < 2 * NST; i += nb * 1024u) ((unsigned*)g_ch[m])[i] = 0;
    if (bl == 0 && t == 0) {
        g_sdone[m] = 0; g_ready[m] = 0; g_cand_cnt[m] = 0;
        g_hiCnt[m] = 0; g_fail[m] = 0; g_eq_cnt[m] = 0;
    }
}

extern "C" void kernel_launch(void* const* d_in, const int* in_sizes, int n_in,
                              void* d_out, int out_size) {
    const float* A = (const float*)d_in[0];
    const float* B = (const float*)d_in[1];
    float* out = (float*)d_out;

    int n = in_sizes[0];
    int n4 = n / 4;
    unsigned j = (unsigned)((1.0 - 0.1) * (double)n);  // mirrors int((1-k)*n)
    unsigned target_top = (unsigned)n - j;             // # of ones
    int n4s = n4 / 16;                                 // 1/16 sample
    int chunk = n4s / 64;                              // float4s per sample block
    unsigned ns = (unsigned)chunk * 64u * 4u;          // sampled element count
    unsigned k_s = (unsigned)((double)target_top * (double)ns / (double)n);
    unsigned margin = 2500u;                           // ~8 sigma
    unsigned C_hi = k_s + margin; if (C_hi > ns) C_hi = ns;
    unsigned C_lo = (k_s > margin) ? (k_s - margin) : 1u;

    mega_kernel<<<2048, 512>>>((const float4*)A, (const float4*)B, (float4*)out,
                               n4, chunk, C_lo, C_hi);
    refine_kernel<<<64, 1024>>>(A, B, out, n, target_top);
}

// round 11
// speedup vs baseline: 1.4919x; 1.4919x over previous
#include <cuda_runtime.h>
#include <cuda_bf16.h>

// Two-launch top-10% mask. R7 mega skeleton + two-level SMEM-sampled band.
// K1 (mega, 2048x512): blocks 0..255 sample 1/16 (128 blocks/matrix):
//   stage A: 8192-bin smem hist (bits 29..17) -> merged -> coarse band
//            [Plo,Phi) at +-2048-sample margins; published via g_prelim.
//   stage B: re-read own chunk (L2-hot), smem-hist band keys into 4096 fine
//            bins + count >=Phi -> fine band [Tlo,Thi) (~66K elements);
//            published via g_ready. Other blocks spin on g_ready only.
//   Then ALL 2048 blocks: fused pass = provisional mask (k>=Tlo -> 1),
//   count k>=Thi, compact band elements per-block -> global candidate list.
// K2 (refine, 16x1024): 8 blocks/matrix, grid barriers: two narrowing
//   stages -> exact threshold key T + residual z; final candidate pass;
//   block 0 stable argsort tie fixup; guarded single-block exact rescue on
//   any detected bound failure (correctness unconditional).
// State self-cleans across graph replays.

#define NB1      8192
#define SHIFT1   17
#define NFB      4096
#define NST      2048
#define CAND_CAP (1u << 19)
#define BLK_CAP  1024
#define EQ_CAP   4096
#define TPB      512

__device__ unsigned g_shist[2][NB1];
__device__ unsigned g_fhist[2][NFB];
__device__ unsigned g_above[2];
__device__ unsigned g_Plo[2], g_Phi[2];
__device__ unsigned g_Tlo[2], g_Thi[2];
__device__ unsigned g_sdone[2], g_sdone2[2];
__device__ unsigned g_prelim[2], g_ready[2];
__device__ unsigned g_ch[2][2][NST];
__device__ unsigned g_cand_idx[2][CAND_CAP];
__device__ unsigned g_cand_key[2][CAND_CAP];
__device__ unsigned g_cand_cnt[2];
__device__ unsigned g_hiCnt[2];
__device__ unsigned g_fail[2];
__device__ unsigned g_bar[2][8];
__device__ unsigned g_eq[2][EQ_CAP];
__device__ unsigned g_eq_cnt[2];

__device__ __forceinline__ unsigned abskey(float v) {
    return __float_as_uint(v) & 0x7FFFFFFFu;
}

// 512-thread inclusive scan of tot[0..511].
__device__ __forceinline__ void scan512(unsigned* tot) {
    const int t = threadIdx.x;
    for (int off = 1; off < TPB; off <<= 1) {
        unsigned x = (t >= off) ? tot[t - off] : 0u;
        __syncthreads();
        tot[t] += x;
        __syncthreads();
    }
}

// Whole-block select over 512*PER bins: bin containing ascending rank S-sub.
// Returns 0 if S < sub (caller's feasibility checks catch any fallout).
template <int PER>
__device__ unsigned block_sel(const unsigned* __restrict__ h, unsigned sub,
                              unsigned* tot) {
    __shared__ unsigned ssel;
    const int t = threadIdx.x;
    if (t == 0) ssel = 0;
    unsigned loc[PER], sum = 0;
    #pragma unroll
    for (int i = 0; i < PER; i++) { loc[i] = h[t * PER + i]; sum += loc[i]; }
    tot[t] = sum;
    __syncthreads();
    scan512(tot);
    unsigned S = tot[TPB - 1];
    if (S >= sub) {
        unsigned rank = S - sub;
        unsigned run = tot[t] - sum;
        #pragma unroll
        for (int i = 0; i < PER; i++) {
            if (run <= rank && rank < run + loc[i]) ssel = (unsigned)(t * PER + i);
            run += loc[i];
        }
    }
    __syncthreads();
    unsigned r = ssel;
    __syncthreads();
    return r;
}

__global__ void __launch_bounds__(TPB)
mega_kernel(const float4* __restrict__ A, const float4* __restrict__ B,
            float4* __restrict__ out, int n4, int chunk,
            unsigned C_lo, unsigned C_hi) {
    __shared__ unsigned sh[NB1];                 // stage hists + scan scratch
    __shared__ unsigned s_idx[BLK_CAP];
    __shared__ unsigned s_key[BLK_CAP];
    __shared__ unsigned s_cnt, s_base, s_hi, s_flag, s_above;
    const int m = blockIdx.x & 1;
    const int t = threadIdx.x;

    // Reset K2's barrier counters for the NEXT refine launch.
    if (blockIdx.x == 0 && t < 16) ((unsigned*)g_bar)[t] = 0;

    // ---- sample phase (blocks 0..255; 128 per matrix) ----
    if (blockIdx.x < 256) {
        const float4* __restrict__ in = m ? B : A;
        const int sbl = blockIdx.x >> 1;          // 0..127
        const int beg = sbl * chunk, end = beg + chunk;

        // stage A: coarse smem hist (bits 29..17; keys < 2^30 -> bin < 8192)
        for (int i = t; i < NB1; i += TPB) sh[i] = 0;
        __syncthreads();
        for (int i = beg + t; i < end; i += TPB) {
            float4 v = in[i];
            atomicAdd(&sh[abskey(v.x) >> SHIFT1], 1u);
            atomicAdd(&sh[abskey(v.y) >> SHIFT1], 1u);
            atomicAdd(&sh[abskey(v.z) >> SHIFT1], 1u);
            atomicAdd(&sh[abskey(v.w) >> SHIFT1], 1u);
        }
        __syncthreads();
        for (int i = t; i < NB1; i += TPB) {
            unsigned c = sh[i];
            if (c) atomicAdd(&g_shist[m][i], c);
        }
        __threadfence();
        __syncthreads();
        if (t == 0) s_flag = (atomicAdd(&g_sdone[m], 1u) == 127u) ? 1u : 0u;
        __syncthreads();
        if (s_flag) {
            __threadfence();
            unsigned binA = block_sel<16>(g_shist[m], C_hi, sh);
            unsigned binB = block_sel<16>(g_shist[m], C_lo, sh);
            if (t == 0) {
                g_Plo[m] = binA << SHIFT1;
                g_Phi[m] = (binB >= NB1 - 1) ? 0x40000000u
                                             : ((binB + 1u) << SHIFT1);
                __threadfence();
                atomicExch(&g_prelim[m], 1u);
            }
        }
        // wait for coarse band
        if (t == 0) {
            while (*(volatile unsigned*)&g_prelim[m] == 0u) __nanosleep(128);
        }
        __syncthreads();
        __threadfence();
        const unsigned Plo = *(volatile unsigned*)&g_Plo[m];
        const unsigned Phi = *(volatile unsigned*)&g_Phi[m];
        const unsigned pspan = Phi - Plo;
        const unsigned sf = (pspan <= (unsigned)NFB)
                                ? 0u : (unsigned)(32 - __clz(pspan - 1) - 12);

        // stage B: fine smem hist over band + count >= Phi (chunk is L2-hot)
        for (int i = t; i < NFB; i += TPB) sh[i] = 0;
        if (t == 0) s_above = 0;
        __syncthreads();
        unsigned above = 0;
        for (int i = beg + t; i < end; i += TPB) {
            float4 v = in[i];
            unsigned k;
            k = abskey(v.x); if (k >= Phi) above++; else if (k >= Plo) atomicAdd(&sh[(k - Plo) >> sf], 1u);
            k = abskey(v.y); if (k >= Phi) above++; else if (k >= Plo) atomicAdd(&sh[(k - Plo) >> sf], 1u);
            k = abskey(v.z); if (k >= Phi) above++; else if (k >= Plo) atomicAdd(&sh[(k - Plo) >> sf], 1u);
            k = abskey(v.w); if (k >= Phi) above++; else if (k >= Plo) atomicAdd(&sh[(k - Plo) >> sf], 1u);
        }
        for (int off = 16; off > 0; off >>= 1) above += __shfl_down_sync(0xFFFFFFFFu, above, off);
        if ((t & 31) == 0 && above) atomicAdd(&s_above, above);
        __syncthreads();
        for (int i = t; i < NFB; i += TPB) {
            unsigned c = sh[i];
            if (c) atomicAdd(&g_fhist[m][i], c);
        }
        if (t == 0 && s_above) atomicAdd(&g_above[m], s_above);
        __threadfence();
        __syncthreads();
        if (t == 0) s_flag = (atomicAdd(&g_sdone2[m], 1u) == 127u) ? 1u : 0u;
        __syncthreads();
        if (s_flag) {
            __threadfence();
            unsigned ab = *(volatile unsigned*)&g_above[m];
            unsigned subA = (C_hi > ab) ? (C_hi - ab) : 0u;
            unsigned subB = (C_lo > ab) ? (C_lo - ab) : 0u;
            unsigned binA2 = block_sel<8>(g_fhist[m], subA, sh);
            unsigned binB2 = block_sel<8>(g_fhist[m], subB, sh);
            if (t == 0) {
                unsigned tlo = (subA == 0) ? Plo : (Plo + (binA2 << sf));
                unsigned thi = (subB == 0) ? Phi : (Plo + ((binB2 + 1u) << sf));
                if (thi > Phi) thi = Phi;
                if (tlo >= thi) { tlo = Plo; thi = Phi; }   // conservative
                g_Tlo[m] = tlo;
                g_Thi[m] = thi;
                __threadfence();
                atomicExch(&g_ready[m], 1u);
            }
        }
    }

    // ---- wait for fine band ----
    if (t == 0) {
        while (*(volatile unsigned*)&g_ready[m] == 0u) __nanosleep(128);
        s_cnt = 0; s_hi = 0;
    }
    __syncthreads();
    __threadfence();
    const unsigned Tlo = *(volatile unsigned*)&g_Tlo[m];
    const unsigned Thi = *(volatile unsigned*)&g_Thi[m];

    // ---- fused pass: mask write + hi count + band compaction ----
    const float4* __restrict__ in = m ? B : A;
    float4* __restrict__ dst = out + (size_t)m * (size_t)n4;
    unsigned hi = 0;
    const int stride = (gridDim.x >> 1) * blockDim.x;
    int i0 = (blockIdx.x >> 1) * blockDim.x + t;
    for (int i = i0; i < n4; i += 2 * stride) {
        int i2 = i + stride;
        float4 v0 = in[i];
        float4 v1 = (i2 < n4) ? in[i2] : make_float4(0.f, 0.f, 0.f, 0.f);
        float4 r0, r1;
        unsigned b0 = ((unsigned)i) << 2;
        unsigned b1 = ((unsigned)i2) << 2;
        unsigned k;

        k = abskey(v0.x); r0.x = (k >= Tlo) ? 1.0f : 0.0f; hi += (k >= Thi);
        if (k >= Tlo && k < Thi) { unsigned p = atomicAdd(&s_cnt, 1u); if (p < BLK_CAP) { s_idx[p] = b0;     s_key[p] = k; } }
        k = abskey(v0.y); r0.y = (k >= Tlo) ? 1.0f : 0.0f; hi += (k >= Thi);
        if (k >= Tlo && k < Thi) { unsigned p = atomicAdd(&s_cnt, 1u); if (p < BLK_CAP) { s_idx[p] = b0 + 1; s_key[p] = k; } }
        k = abskey(v0.z); r0.z = (k >= Tlo) ? 1.0f : 0.0f; hi += (k >= Thi);
        if (k >= Tlo && k < Thi) { unsigned p = atomicAdd(&s_cnt, 1u); if (p < BLK_CAP) { s_idx[p] = b0 + 2; s_key[p] = k; } }
        k = abskey(v0.w); r0.w = (k >= Tlo) ? 1.0f : 0.0f; hi += (k >= Thi);
        if (k >= Tlo && k < Thi) { unsigned p = atomicAdd(&s_cnt, 1u); if (p < BLK_CAP) { s_idx[p] = b0 + 3; s_key[p] = k; } }
        dst[i] = r0;

        if (i2 < n4) {
            k = abskey(v1.x); r1.x = (k >= Tlo) ? 1.0f : 0.0f; hi += (k >= Thi);
            if (k >= Tlo && k < Thi) { unsigned p = atomicAdd(&s_cnt, 1u); if (p < BLK_CAP) { s_idx[p] = b1;     s_key[p] = k; } }
            k = abskey(v1.y); r1.y = (k >= Tlo) ? 1.0f : 0.0f; hi += (k >= Thi);
            if (k >= Tlo && k < Thi) { unsigned p = atomicAdd(&s_cnt, 1u); if (p < BLK_CAP) { s_idx[p] = b1 + 1; s_key[p] = k; } }
            k = abskey(v1.z); r1.z = (k >= Tlo) ? 1.0f : 0.0f; hi += (k >= Thi);
            if (k >= Tlo && k < Thi) { unsigned p = atomicAdd(&s_cnt, 1u); if (p < BLK_CAP) { s_idx[p] = b1 + 2; s_key[p] = k; } }
            k = abskey(v1.w); r1.w = (k >= Tlo) ? 1.0f : 0.0f; hi += (k >= Thi);
            if (k >= Tlo && k < Thi) { unsigned p = atomicAdd(&s_cnt, 1u); if (p < BLK_CAP) { s_idx[p] = b1 + 3; s_key[p] = k; } }
            dst[i2] = r1;
        }
    }
    for (int off = 16; off > 0; off >>= 1) hi += __shfl_down_sync(0xFFFFFFFFu, hi, off);
    if ((t & 31) == 0 && hi) atomicAdd(&s_hi, hi);
    __syncthreads();
    if (t == 0) {
        if (s_hi) atomicAdd(&g_hiCnt[m], s_hi);
        unsigned c = s_cnt;
        if (c > BLK_CAP) { atomicExch(&g_fail[m], 1u); c = BLK_CAP; }
        s_cnt = c;
        s_base = atomicAdd(&g_cand_cnt[m], c);
    }
    __syncthreads();
    unsigned c = s_cnt, bpos = s_base;
    for (unsigned p = t; p < c; p += blockDim.x) {
        unsigned gp = bpos + p;
        if (gp < CAND_CAP) { g_cand_idx[m][gp] = s_idx[p]; g_cand_key[m][gp] = s_key[p]; }
    }
}

// Grid barrier over the nb co-resident blocks of matrix m.
__device__ __forceinline__ void gbar(int m, int ph, unsigned nb) {
    __syncthreads();
    if (threadIdx.x == 0) {
        __threadfence();
        atomicAdd(&g_bar[m][ph], 1u);
        while (*(volatile unsigned*)&g_bar[m][ph] < nb) __nanosleep(64);
        __threadfence();
    }
    __syncthreads();
}

// Single-block, slow, unconditionally-correct rescue (only on bound failure).
__device__ void rescue_block(const float* __restrict__ in, float* __restrict__ dst,
                             int n, unsigned target_top, unsigned* sh) {
    __shared__ unsigned r_lo, r_span, r_rank;
    const int t = threadIdx.x;
    if (t == 0) { r_lo = 0; r_span = 1u << 30; r_rank = (unsigned)n - target_top; }
    __syncthreads();
    while (r_span > 1) {
        unsigned lo = r_lo, span = r_span;
        unsigned s = (span > (unsigned)NST) ? (unsigned)(32 - __clz(span - 1) - 11) : 0u;
        for (int i = t; i < NST; i += 1024) sh[i] = 0;
        __syncthreads();
        for (int i = t; i < n; i += 1024) {
            unsigned d = abskey(in[i]) - lo;
            if (d < span) atomicAdd(&sh[d >> s], 1u);
        }
        __syncthreads();
        if (t == 0) {
            unsigned rank = r_rank, run = 0;
            for (int i = 0; i < NST; i++) {
                unsigned cc = sh[i];
                if (rank < run + cc) { r_lo = lo + ((unsigned)i << s); r_span = 1u << s; r_rank = rank - run; break; }
                run += cc;
            }
        }
        __syncthreads();
    }
    unsigned T = r_lo, z = r_rank;
    for (int i = t; i < n; i += 1024) {
        unsigned k = abskey(in[i]);
        if (k != T) dst[i] = (k > T) ? 1.0f : 0.0f;
    }
    __syncthreads();
    if (t == 0) {
        unsigned seen = 0;
        for (int i = 0; i < n; i++)
            if (abskey(in[i]) == T) { dst[i] = (seen < z) ? 0.0f : 1.0f; seen++; }
    }
    __syncthreads();
}

__global__ void __launch_bounds__(1024)
refine_kernel(const float* __restrict__ A, const float* __restrict__ B,
              float* __restrict__ out, int n, unsigned target_top) {
    __shared__ unsigned sh[NST];
    __shared__ unsigned s_sel, s_res;
    const int m = blockIdx.x & 1;
    const unsigned nb = gridDim.x >> 1;   // 8
    const unsigned bl = blockIdx.x >> 1;
    const int t = threadIdx.x;

    unsigned cnt_real = g_cand_cnt[m];
    unsigned cnt = min(cnt_real, CAND_CAP);
    unsigned hic = g_hiCnt[m];
    bool bad = (g_fail[m] != 0) || (cnt_real > CAND_CAP) ||
               (hic >= target_top) || (target_top - hic > cnt);
    unsigned rank = 0, lo = 0, span = 1;
    if (!bad) {
        unsigned keep = target_top - hic;
        rank = cnt - keep;
        lo = g_Tlo[m];
        span = g_Thi[m] - lo;
    }
    if (!bad && span > (1u << 22)) bad = true;
    const unsigned* __restrict__ keys = g_cand_key[m];
    const unsigned* __restrict__ idxs = g_cand_idx[m];
    float* __restrict__ dst = out + (size_t)m * (size_t)n;

    // two narrowing stages (2048 bins each; covers span <= 4M)
    for (int st = 0; st < 2; st++) {
        bool active = (!bad) && (span > 1);
        unsigned s = 0;
        if (active) {
            s = (span > (unsigned)NST) ? (unsigned)(32 - __clz(span - 1) - 11) : 0u;
            for (int i = t; i < NST; i += 1024) sh[i] = 0;
            __syncthreads();
            unsigned stride = nb * 1024u;
            for (unsigned c = bl * 1024u + t; c < cnt; c += stride) {
                unsigned d = keys[c] - lo;
                if (d < span) atomicAdd(&sh[d >> s], 1u);
            }
            __syncthreads();
            for (int i = t; i < NST; i += 1024) {
                unsigned v = sh[i];
                if (v) atomicAdd(&g_ch[m][st][i], v);
            }
        }
        gbar(m, st, nb);
        if (active) {
            unsigned l0 = g_ch[m][st][2 * t], l1 = g_ch[m][st][2 * t + 1];
            unsigned sum = l0 + l1;
            if (t == 0) { s_sel = 0; s_res = 0; }
            __syncthreads();
            sh[t] = sum;
            __syncthreads();
            for (int off = 1; off < 1024; off <<= 1) {
                unsigned x = (t >= off) ? sh[t - off] : 0u;
                __syncthreads();
                sh[t] += x;
                __syncthreads();
            }
            unsigned incl = sh[t], run = incl - sum;
            if (run <= rank && rank < run + l0)           { s_sel = 2 * t;     s_res = rank - run; }
            else if (run + l0 <= rank && rank < incl)     { s_sel = 2 * t + 1; s_res = rank - run - l0; }
            __syncthreads();
            lo += s_sel << s;
            span = 1u << s;
            rank = s_res;
            __syncthreads();
        }
    }
    if (!bad && span != 1) bad = true;

    // final candidate pass
    if (!bad) {
        const unsigned T = lo;
        unsigned stride = nb * 1024u;
        for (unsigned c = bl * 1024u + t; c < cnt; c += stride) {
            unsigned k = keys[c];
            if (k < T) {
                dst[idxs[c]] = 0.0f;
            } else if (k == T) {
                unsigned p = atomicAdd(&g_eq_cnt[m], 1u);
                if (p < EQ_CAP) g_eq[m][p] = idxs[c];
            }
        }
    }
    gbar(m, 2, nb);
    unsigned eq = g_eq_cnt[m];
    if (!bad && eq > EQ_CAP) bad = true;
    if (bl == 0) {
        if (!bad) {
            unsigned z = rank;
            for (unsigned e = t; e < eq; e += 1024) {
                unsigned idx = g_eq[m][e];
                unsigned c2 = 0;
                for (unsigned q = 0; q < eq; q++) c2 += (g_eq[m][q] < idx) ? 1u : 0u;
                if (c2 < z) dst[idx] = 0.0f;
            }
        } else {
            rescue_block(m ? B : A, dst, n, target_top, sh);
        }
    }
    gbar(m, 3, nb);

    // self-clean for next replay's mega_kernel (g_bar reset there)
    unsigned tstride = nb * 1024u;
    for (unsigned i = bl * 1024u + t; i < NB1; i += tstride) g_shist[m][i] = 0;
    for (unsigned i = bl * 1024u + t; i < NFB; i += tstride) g_fhist[m][i] = 0;
    for (unsigned i = bl * 1024u + t; i < 2 * NST; i += tstride) ((unsigned*)g_ch[m])[i] = 0;
    if (bl == 0 && t == 0) {
        g_sdone[m] = 0; g_sdone2[m] = 0; g_prelim[m] = 0; g_ready[m] = 0;
        g_above[m] = 0; g_cand_cnt[m] = 0; g_hiCnt[m] = 0; g_fail[m] = 0;
        g_eq_cnt[m] = 0;
    }
}

extern "C" void kernel_launch(void* const* d_in, const int* in_sizes, int n_in,
                              void* d_out, int out_size) {
    const float* A = (const float*)d_in[0];
    const float* B = (const float*)d_in[1];
    float* out = (float*)d_out;

    int n = in_sizes[0];
    int n4 = n / 4;
    unsigned j = (unsigned)((1.0 - 0.1) * (double)n);  // mirrors int((1-k)*n)
    unsigned target_top = (unsigned)n - j;             // # of ones
    int n4s = n4 / 16;                                 // 1/16 sample
    int chunk = n4s / 128;                             // float4s per sample block
    unsigned ns = (unsigned)chunk * 128u * 4u;         // sampled element count
    unsigned k_s = (unsigned)((double)target_top * (double)ns / (double)n);
    unsigned margin = 2048u;                           // ~6.5 sigma
    unsigned C_hi = k_s + margin; if (C_hi > ns) C_hi = ns;
    unsigned C_lo = (k_s > margin) ? (k_s - margin) : 1u;

    mega_kernel<<<2048, TPB>>>((const float4*)A, (const float4*)B, (float4*)out,
                               n4, chunk, C_lo, C_hi);
    refine_kernel<<<16, 1024>>>(A, B, out, n, target_top);
}